// round 2
// baseline (speedup 1.0000x reference)
#include <cuda_runtime.h>
#include <cuda_bf16.h>
#include <float.h>

#define MAX_N 8192
#define BLOCK 256

__device__ float g_row_loss[MAX_N];

__global__ __launch_bounds__(BLOCK)
void triplet_row_kernel(const float* __restrict__ sim,
                        const int* __restrict__ targets,
                        const int* __restrict__ idx,
                        int n) {
    __shared__ int s_t[MAX_N];
    __shared__ float s_pos[BLOCK / 32];
    __shared__ float s_neg[BLOCK / 32];

    const int row = blockIdx.x;
    const int tid = threadIdx.x;

    // Stage targets (int32) into shared memory: 32 KB, L2-resident across blocks.
    #pragma unroll 8
    for (int j = tid; j < n; j += BLOCK) s_t[j] = targets[j];
    __syncthreads();

    const int my_t = s_t[row];            // targets[row]
    const int self_col = idx[row];        // row of sim to read == self column
    const float* __restrict__ rp = sim + (size_t)self_col * (size_t)n;

    float pos =  FLT_MAX;   // hardest positive (min over same-class, excl self)
    float neg = -FLT_MAX;   // hardest negative (max over diff-class)

    // Stream the row: consecutive threads read consecutive float4s.
    for (int base = 0; base < n; base += BLOCK * 4) {
        const int j = base + tid * 4;
        const float4 v = *reinterpret_cast<const float4*>(rp + j);
        const int4   t = *reinterpret_cast<const int4*>(&s_t[j]);

        if (t.x == my_t) { if (j + 0 != self_col) pos = fminf(pos, v.x); }
        else             { neg = fmaxf(neg, v.x); }
        if (t.y == my_t) { if (j + 1 != self_col) pos = fminf(pos, v.y); }
        else             { neg = fmaxf(neg, v.y); }
        if (t.z == my_t) { if (j + 2 != self_col) pos = fminf(pos, v.z); }
        else             { neg = fmaxf(neg, v.z); }
        if (t.w == my_t) { if (j + 3 != self_col) pos = fminf(pos, v.w); }
        else             { neg = fmaxf(neg, v.w); }
    }

    // Warp reduction
    #pragma unroll
    for (int off = 16; off > 0; off >>= 1) {
        pos = fminf(pos, __shfl_xor_sync(0xFFFFFFFFu, pos, off));
        neg = fmaxf(neg, __shfl_xor_sync(0xFFFFFFFFu, neg, off));
    }
    const int wid = tid >> 5;
    const int lid = tid & 31;
    if (lid == 0) { s_pos[wid] = pos; s_neg[wid] = neg; }
    __syncthreads();

    if (wid == 0) {
        pos = (lid < BLOCK / 32) ? s_pos[lid] :  FLT_MAX;
        neg = (lid < BLOCK / 32) ? s_neg[lid] : -FLT_MAX;
        #pragma unroll
        for (int off = 4; off > 0; off >>= 1) {
            pos = fminf(pos, __shfl_xor_sync(0xFFFFFFFFu, pos, off));
            neg = fmaxf(neg, __shfl_xor_sync(0xFFFFFFFFu, neg, off));
        }
        if (lid == 0) {
            g_row_loss[row] = fmaxf(neg - pos + 0.1f, 0.0f);
        }
    }
}

__global__ __launch_bounds__(BLOCK)
void mean_reduce_kernel(float* __restrict__ out, int n) {
    __shared__ double s_sum[BLOCK];
    const int tid = threadIdx.x;
    double acc = 0.0;
    for (int j = tid; j < n; j += BLOCK) acc += (double)g_row_loss[j];
    s_sum[tid] = acc;
    __syncthreads();
    #pragma unroll
    for (int s = BLOCK / 2; s > 0; s >>= 1) {
        if (tid < s) s_sum[tid] += s_sum[tid + s];
        __syncthreads();
    }
    if (tid == 0) out[0] = (float)(s_sum[0] / (double)n);
}

extern "C" void kernel_launch(void* const* d_in, const int* in_sizes, int n_in,
                              void* d_out, int out_size) {
    const float* sim     = (const float*)d_in[0];
    const int*   targets = (const int*)d_in[1];
    const int*   idx     = (const int*)d_in[2];
    float* out = (float*)d_out;

    const int n = in_sizes[1];   // 8192

    triplet_row_kernel<<<n, BLOCK>>>(sim, targets, idx, n);
    mean_reduce_kernel<<<1, BLOCK>>>(out, n);
}

// round 3
// speedup vs baseline: 1.2200x; 1.2200x over previous
#include <cuda_runtime.h>
#include <cuda_bf16.h>
#include <float.h>

#define MAX_N 8192
#define BLOCK 256
#define ROWS_PER_BLOCK 8   // one row per warp

__device__ float g_row_loss[MAX_N];

__global__ __launch_bounds__(BLOCK)
void triplet_row_kernel(const float* __restrict__ sim,
                        const int* __restrict__ targets,
                        const int* __restrict__ idx,
                        int n) {
    __shared__ int s_t[MAX_N];

    const int tid = threadIdx.x;
    const int wid = tid >> 5;
    const int lid = tid & 31;

    // Stage targets once per block (32 KB from L2; 8x less traffic than before).
    #pragma unroll 8
    for (int j = tid; j < n; j += BLOCK) s_t[j] = targets[j];
    __syncthreads();

    const int row = blockIdx.x * ROWS_PER_BLOCK + wid;
    if (row >= n) return;

    const int my_t = s_t[row];
    const int self_col = idx[row];
    const float* __restrict__ rp = sim + (size_t)self_col * (size_t)n;

    float pos =  FLT_MAX;
    float neg = -FLT_MAX;

    // Warp streams the whole row: 8192 elems = 64 float4-iters of 32 lanes.
    // Unroll 4 -> 4 independent float4 loads in flight per thread.
    #pragma unroll 4
    for (int it = 0; it < n / (32 * 4); it++) {
        const int j = it * 128 + lid * 4;
        const float4 v = *reinterpret_cast<const float4*>(rp + j);
        const int4   t = *reinterpret_cast<const int4*>(&s_t[j]);

        if (t.x == my_t) { if (j + 0 != self_col) pos = fminf(pos, v.x); }
        else             { neg = fmaxf(neg, v.x); }
        if (t.y == my_t) { if (j + 1 != self_col) pos = fminf(pos, v.y); }
        else             { neg = fmaxf(neg, v.y); }
        if (t.z == my_t) { if (j + 2 != self_col) pos = fminf(pos, v.z); }
        else             { neg = fmaxf(neg, v.z); }
        if (t.w == my_t) { if (j + 3 != self_col) pos = fminf(pos, v.w); }
        else             { neg = fmaxf(neg, v.w); }
    }

    // Warp-only reduction (no block barriers in the hot path).
    #pragma unroll
    for (int off = 16; off > 0; off >>= 1) {
        pos = fminf(pos, __shfl_xor_sync(0xFFFFFFFFu, pos, off));
        neg = fmaxf(neg, __shfl_xor_sync(0xFFFFFFFFu, neg, off));
    }
    if (lid == 0) {
        g_row_loss[row] = fmaxf(neg - pos + 0.1f, 0.0f);
    }
}

__global__ __launch_bounds__(1024)
void mean_reduce_kernel(float* __restrict__ out, int n) {
    __shared__ float s_sum[32];
    const int tid = threadIdx.x;
    const int wid = tid >> 5;
    const int lid = tid & 31;

    // n = 8192 floats = 2048 float4; 1024 threads x 2 float4 each.
    const float4* rl = reinterpret_cast<const float4*>(g_row_loss);
    float4 a = rl[tid];
    float4 b = rl[tid + 1024];
    float acc = ((a.x + a.y) + (a.z + a.w)) + ((b.x + b.y) + (b.z + b.w));

    #pragma unroll
    for (int off = 16; off > 0; off >>= 1)
        acc += __shfl_xor_sync(0xFFFFFFFFu, acc, off);
    if (lid == 0) s_sum[wid] = acc;
    __syncthreads();

    if (wid == 0) {
        acc = s_sum[lid];
        #pragma unroll
        for (int off = 16; off > 0; off >>= 1)
            acc += __shfl_xor_sync(0xFFFFFFFFu, acc, off);
        if (lid == 0) out[0] = acc / (float)n;
    }
}

extern "C" void kernel_launch(void* const* d_in, const int* in_sizes, int n_in,
                              void* d_out, int out_size) {
    const float* sim     = (const float*)d_in[0];
    const int*   targets = (const int*)d_in[1];
    const int*   idx     = (const int*)d_in[2];
    float* out = (float*)d_out;

    const int n = in_sizes[1];   // 8192

    triplet_row_kernel<<<n / ROWS_PER_BLOCK, BLOCK>>>(sim, targets, idx, n);
    mean_reduce_kernel<<<1, 1024>>>(out, n);
}